// round 14
// baseline (speedup 1.0000x reference)
#include <cuda_runtime.h>
#include <cuda_bf16.h>
#include <math.h>
#include <stdint.h>

// Problem constants
#define NND   65536      // N nodes
#define DD    256        // feature dim
#define NSS   512        // edge slots
#define EPS_LN   1e-5f
#define EPS_ATTN 1e-8f

// Output layout: [x_out (N*D)] [H (N*NS)] [dots2 (N*NS)]
#define OFF_H   ((size_t)NND * DD)
#define OFF_D2  (OFF_H + (size_t)NND * NSS)

// ------------------------- device scratch (no allocations allowed) -------
__device__ float g_xin[(size_t)NND * DD];          // 64 MB  LN(x)
__device__ float g_qkv[(size_t)NND * 3 * DD];      // 192 MB [q2 | kk | vv] row stride 768
__device__ float g_dots[(size_t)NSS * NND];        // 128 MB edge->node logits
__device__ float g_eln[NSS * DD];
__device__ float g_qe[NSS * DD];
__device__ float g_e2cat[NSS * 2 * DD];            // [e_ln | updates]
__device__ float g_hmlp[NSS * DD];
__device__ float g_enew[NSS * DD];
__device__ float g_k2[NSS * DD];
__device__ float g_eout[NSS * DD];
__device__ float g_wcatT[3 * DD * DD];
__device__ float g_bcat[3 * DD];
// bf16 2-way splits (h + l) for mma.sync GEMM operands
__device__ __nv_bfloat16 g_kk_h[(size_t)NND * DD], g_kk_l[(size_t)NND * DD];
__device__ __nv_bfloat16 g_q2_h[(size_t)NND * DD], g_q2_l[(size_t)NND * DD];
__device__ __nv_bfloat16 g_qe_h[NSS * DD], g_qe_l[NSS * DD];
__device__ __nv_bfloat16 g_k2_h[NSS * DD], g_k2_l[NSS * DD];

// ------------------------- small helpers ---------------------------------
__device__ __forceinline__ unsigned fkey(float f) {
    unsigned u = __float_as_uint(f);
    return (u & 0x80000000u) ? ~u : (u | 0x80000000u);
}
__device__ __forceinline__ float keyToFloat(unsigned k) {
    unsigned u = (k & 0x80000000u) ? (k & 0x7fffffffu) : ~k;
    return __uint_as_float(u);
}
__device__ __forceinline__ uint32_t smem_u32(const void* p) {
    uint32_t a;
    asm("{ .reg .u64 tmp; cvta.to.shared.u64 tmp, %1; cvt.u32.u64 %0, tmp; }"
        : "=r"(a) : "l"(p));
    return a;
}
__device__ __forceinline__ void mma16816(float* d, const uint32_t* a, const uint32_t* b) {
    asm volatile(
        "mma.sync.aligned.m16n8k16.row.col.f32.bf16.bf16.f32 "
        "{%0,%1,%2,%3}, {%4,%5,%6,%7}, {%8,%9}, {%0,%1,%2,%3};\n"
        : "+f"(d[0]), "+f"(d[1]), "+f"(d[2]), "+f"(d[3])
        : "r"(a[0]), "r"(a[1]), "r"(a[2]), "r"(a[3]), "r"(b[0]), "r"(b[1]));
}
__device__ __forceinline__ void ldsm4(uint32_t* r, uint32_t addr) {
    asm volatile("ldmatrix.sync.aligned.m8n8.x4.shared.b16 {%0,%1,%2,%3}, [%4];"
                 : "=r"(r[0]), "=r"(r[1]), "=r"(r[2]), "=r"(r[3]) : "r"(addr));
}
__device__ __forceinline__ void ldsm2(uint32_t* r, uint32_t addr) {
    asm volatile("ldmatrix.sync.aligned.m8n8.x2.shared.b16 {%0,%1}, [%2];"
                 : "=r"(r[0]), "=r"(r[1]) : "r"(addr));
}

// ------------------------- weight prep -----------------------------------
__global__ void prep_wcat(const float* __restrict__ Wq, const float* __restrict__ bq,
                          const float* __restrict__ Wk, const float* __restrict__ bk,
                          const float* __restrict__ Wv, const float* __restrict__ bv) {
    int idx = blockIdx.x * 256 + threadIdx.x;
    int j = idx >> 8, k = idx & 255;
    const float* W = (j < 256) ? Wq : ((j < 512) ? Wk : Wv);
    int jj = j & 255;
    g_wcatT[idx] = W[k * 256 + jj];
    if (k == 0) {
        const float* bb = (j < 256) ? bq : ((j < 512) ? bk : bv);
        g_bcat[j] = bb[jj];
    }
}

// ------------------------- row LayerNorm (nodes) --------------------------
__global__ void node_ln(const float* __restrict__ x, const float* __restrict__ g,
                        const float* __restrict__ b) {
    int row = blockIdx.x, t = threadIdx.x;
    __shared__ float red[256];
    float v = x[(size_t)row * DD + t];
    red[t] = v; __syncthreads();
    for (int s = 128; s > 0; s >>= 1) { if (t < s) red[t] += red[t + s]; __syncthreads(); }
    float mean = red[0] * (1.0f / DD);
    __syncthreads();
    float d = v - mean;
    red[t] = d * d; __syncthreads();
    for (int s = 128; s > 0; s >>= 1) { if (t < s) red[t] += red[t + s]; __syncthreads(); }
    float var = red[0] * (1.0f / DD);
    g_xin[(size_t)row * DD + t] = d * rsqrtf(var + EPS_LN) * g[t] + b[t];
}

// ------------------------- edge prep: sample + LN -------------------------
__global__ void edge_prep(const float* __restrict__ noise, const float* __restrict__ mu,
                          const float* __restrict__ ls, const float* __restrict__ g,
                          const float* __restrict__ b) {
    int row = blockIdx.x, t = threadIdx.x;
    __shared__ float red[256];
    float v = mu[t] + expf(ls[t]) * noise[row * DD + t];
    red[t] = v; __syncthreads();
    for (int s = 128; s > 0; s >>= 1) { if (t < s) red[t] += red[t + s]; __syncthreads(); }
    float mean = red[0] * (1.0f / DD);
    __syncthreads();
    float d = v - mean;
    red[t] = d * d; __syncthreads();
    for (int s = 128; s > 0; s >>= 1) { if (t < s) red[t] += red[t + s]; __syncthreads(); }
    float var = red[0] * (1.0f / DD);
    float o = d * rsqrtf(var + EPS_LN) * g[t] + b[t];
    g_eln[row * DD + t] = o;
    g_e2cat[row * 2 * DD + t] = o;
}

// ------------- small dense: one row per block, 256 output cols ------------
__global__ void rowgemm(const float* __restrict__ X, int ldx, int K,
                        const float* __restrict__ Wm, const float* __restrict__ bias,
                        float* __restrict__ Y, int ldy, int relu) {
    __shared__ float xr[512];
    int row = blockIdx.x, t = threadIdx.x;
    for (int i = t; i < K; i += 256) xr[i] = X[(size_t)row * ldx + i];
    __syncthreads();
    float acc = bias[t];
    for (int k = 0; k < K; k++) acc = fmaf(xr[k], Wm[k * 256 + t], acc);
    if (relu) acc = fmaxf(acc, 0.0f);
    Y[(size_t)row * ldy + t] = acc;
}

// ------------------------- big SGEMM (exact fp32, round-10) ---------------
__global__ void __launch_bounds__(256, 2) sgemm_nt(
        const float* __restrict__ A, int lda,
        const float* __restrict__ B, int ldb,
        float* __restrict__ C, int ldc, int K,
        const float* __restrict__ bias, float scale, int relu_from) {
    __shared__ float As[2][16][132];
    __shared__ float Bs[2][16][132];
    const int tid = threadIdx.x;
    const int bm = blockIdx.y * 128, bn = blockIdx.x * 128;
    const int tx = tid & 15, ty = tid >> 4;
    const int lr = tid & 127;
    const int lk = (tid >> 7) * 8;
    const float* Ag = A + (size_t)(bm + lr) * lda + lk;
    const float* Bg = B + (size_t)(bn + lr) * ldb + lk;

    float acc[8][8] = {};
    float4 a0 = *(const float4*)(Ag);
    float4 a1 = *(const float4*)(Ag + 4);
    float4 b0 = *(const float4*)(Bg);
    float4 b1 = *(const float4*)(Bg + 4);
    As[0][lk + 0][lr] = a0.x; As[0][lk + 1][lr] = a0.y;
    As[0][lk + 2][lr] = a0.z; As[0][lk + 3][lr] = a0.w;
    As[0][lk + 4][lr] = a1.x; As[0][lk + 5][lr] = a1.y;
    As[0][lk + 6][lr] = a1.z; As[0][lk + 7][lr] = a1.w;
    Bs[0][lk + 0][lr] = b0.x; Bs[0][lk + 1][lr] = b0.y;
    Bs[0][lk + 2][lr] = b0.z; Bs[0][lk + 3][lr] = b0.w;
    Bs[0][lk + 4][lr] = b1.x; Bs[0][lk + 5][lr] = b1.y;
    Bs[0][lk + 6][lr] = b1.z; Bs[0][lk + 7][lr] = b1.w;
    __syncthreads();

    const int nIter = K >> 4;
    for (int it = 0; it < nIter; it++) {
        const int cur = it & 1;
        if (it + 1 < nIter) {
            int k0 = (it + 1) << 4;
            a0 = *(const float4*)(Ag + k0);
            a1 = *(const float4*)(Ag + k0 + 4);
            b0 = *(const float4*)(Bg + k0);
            b1 = *(const float4*)(Bg + k0 + 4);
        }
#pragma unroll
        for (int kk = 0; kk < 16; kk++) {
            float a[8], b[8];
            *(float4*)(a)     = *(const float4*)&As[cur][kk][ty * 4];
            *(float4*)(a + 4) = *(const float4*)&As[cur][kk][64 + ty * 4];
            *(float4*)(b)     = *(const float4*)&Bs[cur][kk][tx * 4];
            *(float4*)(b + 4) = *(const float4*)&Bs[cur][kk][64 + tx * 4];
#pragma unroll
            for (int i = 0; i < 8; i++)
#pragma unroll
                for (int j = 0; j < 8; j++)
                    acc[i][j] = fmaf(a[i], b[j], acc[i][j]);
        }
        if (it + 1 < nIter) {
            const int nxt = cur ^ 1;
            As[nxt][lk + 0][lr] = a0.x; As[nxt][lk + 1][lr] = a0.y;
            As[nxt][lk + 2][lr] = a0.z; As[nxt][lk + 3][lr] = a0.w;
            As[nxt][lk + 4][lr] = a1.x; As[nxt][lk + 5][lr] = a1.y;
            As[nxt][lk + 6][lr] = a1.z; As[nxt][lk + 7][lr] = a1.w;
            Bs[nxt][lk + 0][lr] = b0.x; Bs[nxt][lk + 1][lr] = b0.y;
            Bs[nxt][lk + 2][lr] = b0.z; Bs[nxt][lk + 3][lr] = b0.w;
            Bs[nxt][lk + 4][lr] = b1.x; Bs[nxt][lk + 5][lr] = b1.y;
            Bs[nxt][lk + 6][lr] = b1.z; Bs[nxt][lk + 7][lr] = b1.w;
            __syncthreads();
        }
    }
#pragma unroll
    for (int ih = 0; ih < 2; ih++) {
#pragma unroll
        for (int i = 0; i < 4; i++) {
            int row = bm + ih * 64 + ty * 4 + i;
#pragma unroll
            for (int jh = 0; jh < 2; jh++) {
                int col = bn + jh * 64 + tx * 4;
                float4 v;
                float* vp = (float*)&v;
#pragma unroll
                for (int j = 0; j < 4; j++) {
                    float t = acc[ih * 4 + i][jh * 4 + j] * scale;
                    if (bias) t += bias[col + j];
                    if (col + j >= relu_from) t = fmaxf(t, 0.0f);
                    vp[j] = t;
                }
                *(float4*)&C[(size_t)row * ldc + col] = v;
            }
        }
    }
}

// ---------------- split preparation (fp32 -> 2x bf16) ---------------------
__global__ void split_qkv() {   // q2 = cols 0..255, kk = cols 256..511
    int row = blockIdx.x, t = threadIdx.x;
    size_t o = (size_t)row * 256 + t;
    float v1 = g_qkv[(size_t)row * 768 + t];
    __nv_bfloat16 h = __float2bfloat16(v1);
    g_q2_h[o] = h;
    g_q2_l[o] = __float2bfloat16(v1 - __bfloat162float(h));
    float v2 = g_qkv[(size_t)row * 768 + 256 + t];
    h = __float2bfloat16(v2);
    g_kk_h[o] = h;
    g_kk_l[o] = __float2bfloat16(v2 - __bfloat162float(h));
}
__global__ void split_small(const float* __restrict__ src,
                            __nv_bfloat16* __restrict__ h2,
                            __nv_bfloat16* __restrict__ l2) {
    int i = blockIdx.x * 256 + threadIdx.x;
    float v = src[i];
    __nv_bfloat16 h = __float2bfloat16(v);
    h2[i] = h;
    l2[i] = __float2bfloat16(v - __bfloat162float(h));
}

// --- tensor GEMM (legacy mma.sync + ldmatrix): C = scale * A @ B^T --------
// 3-term 2-way bf16 split (hh + hl + lh), ~1.5e-5 relative accuracy.
// A splits [Mtot,256], B splits [Ntot,256] bf16 row-major. Tile 128x128,
// K = 256 processed in 4 chunks of 64. 256 threads, 8 warps (2m x 4n),
// warp tile 64x32 = 4x4 m16n8k16. Smem: 4 tiles x 16KB = 64KB, XOR-swizzled
// 16B chunks (conflict-free STS + LDSM).
__global__ void __launch_bounds__(256) tgemmL3(
        const __nv_bfloat16* __restrict__ Ah, const __nv_bfloat16* __restrict__ Al,
        const __nv_bfloat16* __restrict__ Bh, const __nv_bfloat16* __restrict__ Bl,
        float* __restrict__ C, int ldc, float scale) {
    extern __shared__ char dynsm[];
    const int tid = threadIdx.x;
    const int lane = tid & 31;
    const int wid = tid >> 5;
    const int bm = blockIdx.y * 128;
    const int bn = blockIdx.x * 128;
    const int wm = (wid & 1) * 64;
    const int wn = (wid >> 1) * 32;

    const uint32_t sbase = smem_u32(dynsm);
    const uint32_t sAh = sbase;
    const uint32_t sAl = sbase + 16384;
    const uint32_t sBh = sbase + 32768;
    const uint32_t sBl = sbase + 49152;

    const __nv_bfloat16* gs[4] = {Ah, Al, Bh, Bl};

    float acc[4][4][4];
#pragma unroll
    for (int i = 0; i < 4; i++)
#pragma unroll
        for (int j = 0; j < 4; j++)
#pragma unroll
            for (int r = 0; r < 4; r++) acc[i][j][r] = 0.0f;

    for (int c = 0; c < 4; c++) {
        const int k0 = c * 64;
        // load 4 tiles of 128x64 bf16, swizzled 16B chunks
        for (int v = tid; v < 4096; v += 256) {
            int tile = v >> 10;
            int idx = v & 1023;
            int r = idx >> 3;
            int c16 = idx & 7;
            int base_r = (tile < 2) ? bm : bn;
            const uint4 val = *(const uint4*)(gs[tile] + (size_t)(base_r + r) * 256 + k0 + c16 * 8);
            *(uint4*)(dynsm + tile * 16384 + r * 128 + (((c16 ^ (r & 7))) << 4)) = val;
        }
        __syncthreads();

#pragma unroll
        for (int kk = 0; kk < 4; kk++) {
            // A fragments via ldmatrix.x4
            const int am = lane >> 3;
            const int arow_l = (am & 1) * 8 + (lane & 7);
            const int ac16 = kk * 2 + (am >> 1);
            uint32_t ah[4][4], al_[4][4];
#pragma unroll
            for (int i = 0; i < 4; i++) {
                int row = wm + i * 16 + arow_l;
                uint32_t off = (uint32_t)(row * 128 + ((ac16 ^ (row & 7)) << 4));
                ldsm4(ah[i],  sAh + off);
                ldsm4(al_[i], sAl + off);
            }
            // B fragments via ldmatrix.x2 (lanes 0..15 supply addresses)
            const int brow_l = lane & 7;
            const int bc16 = kk * 2 + ((lane >> 3) & 1);
            uint32_t bh[4][2], bl_[4][2];
#pragma unroll
            for (int j = 0; j < 4; j++) {
                int row = wn + j * 8 + brow_l;
                uint32_t off = (uint32_t)(row * 128 + ((bc16 ^ (row & 7)) << 4));
                ldsm2(bh[j],  sBh + off);
                ldsm2(bl_[j], sBl + off);
            }
#pragma unroll
            for (int i = 0; i < 4; i++)
#pragma unroll
                for (int j = 0; j < 4; j++) {
                    mma16816(acc[i][j], ah[i],  bh[j]);   // hh
                    mma16816(acc[i][j], ah[i],  bl_[j]);  // hl
                    mma16816(acc[i][j], al_[i], bh[j]);   // lh
                }
        }
        __syncthreads();
    }

    // epilogue
    const int g = lane >> 2, q = lane & 3;
#pragma unroll
    for (int i = 0; i < 4; i++) {
        int row0 = bm + wm + i * 16 + g;
#pragma unroll
        for (int j = 0; j < 4; j++) {
            int col = bn + wn + j * 8 + q * 2;
            *(float2*)&C[(size_t)row0 * ldc + col] =
                make_float2(acc[i][j][0] * scale, acc[i][j][1] * scale);
            *(float2*)&C[(size_t)(row0 + 8) * ldc + col] =
                make_float2(acc[i][j][2] * scale, acc[i][j][3] * scale);
        }
    }
}

// ----- edge-side: softmax stats + guarded exact top-k_n + gather ----------
#define DELTA_E 1e-3f
__global__ void __launch_bounds__(1024) edge_select(const int* __restrict__ kn_ptr) {
    const int row = blockIdx.x;
    const int t = threadIdx.x;
    const float* dr = g_dots + (size_t)row * NND;
    __shared__ float red[1024];
    __shared__ unsigned hist[2048];
    __shared__ unsigned sb_bin;
    __shared__ int sb_rem;

    for (int i = t; i < 2048; i += 1024) hist[i] = 0;
    __syncthreads();
    float m = -3.0e38f, s = 0.0f;
    for (int i = t; i < NND; i += 1024) {
        float dv = dr[i];
        if (dv > m) { s = s * expf(m - dv) + 1.0f; m = dv; }
        else        { s += expf(dv - m); }
        atomicAdd(&hist[fkey(dv) >> 21], 1u);
    }
    red[t] = m; __syncthreads();
    for (int st = 512; st > 0; st >>= 1) { if (t < st) red[t] = fmaxf(red[t], red[t + st]); __syncthreads(); }
    float M = red[0]; __syncthreads();
    red[t] = s * expf(m - M); __syncthreads();
    for (int st = 512; st > 0; st >>= 1) { if (t < st) red[t] += red[t + st]; __syncthreads(); }
    float Z = red[0]; __syncthreads();

    int kq = *kn_ptr;
    unsigned pref = 0, pmask = 0;
    int rem = kq;
    if (t == 0) {
        int cum = 0, b = 2047;
        for (; b >= 0; b--) { cum += (int)hist[b]; if (cum >= rem) break; }
        if (b < 0) b = 0;
        sb_bin = (unsigned)b;
        sb_rem = rem - (cum - (int)hist[b]);
    }
    __syncthreads();
    pref = sb_bin << 21;
    pmask = 2047u << 21;
    rem = sb_rem;
    __syncthreads();

    const int shifts[2] = {10, 0};
    const int bcnts[2]  = {2048, 1024};
    for (int p = 0; p < 2; p++) {
        int bc = bcnts[p], sh = shifts[p];
        for (int i = t; i < bc; i += 1024) hist[i] = 0;
        __syncthreads();
        for (int i = t; i < NND; i += 1024) {
            unsigned key = fkey(dr[i]);
            if ((key & pmask) == pref) atomicAdd(&hist[(key >> sh) & (bc - 1)], 1u);
        }
        __syncthreads();
        if (t == 0) {
            int cum = 0, b = bc - 1;
            for (; b >= 0; b--) { cum += (int)hist[b]; if (cum >= rem) break; }
            if (b < 0) b = 0;
            sb_bin = (unsigned)b;
            sb_rem = rem - (cum - (int)hist[b]);
        }
        __syncthreads();
        pref |= sb_bin << sh;
        pmask |= (unsigned)(bc - 1) << sh;
        rem = sb_rem;
        __syncthreads();
    }

    __shared__ int cnt;
    __shared__ int sidx[256];
    if (t == 0) cnt = 0;
    __syncthreads();
    unsigned klow = fkey(keyToFloat(pref) - DELTA_E);
    for (int i = t; i < NND; i += 1024) {
        if (fkey(dr[i]) >= klow) {
            int p = atomicAdd(&cnt, 1);
            if (p < 256) sidx[p] = i;
        }
    }
    __syncthreads();
    int nc = cnt < 256 ? cnt : 256;

    __shared__ float qs[256];
    if (t < 256) qs[t] = g_qe[row * DD + t];
    __syncthreads();
    __shared__ float dex[256];
    if (t < nc) {
        const float* kkp = g_qkv + (size_t)sidx[t] * 768 + 256;
        float acc = 0.0f;
#pragma unroll 8
        for (int k = 0; k < 256; k++) acc = fmaf(qs[k], kkp[k], acc);
        dex[t] = acc * 0.0625f;
    }
    __syncthreads();

    __shared__ int   selI[128];
    __shared__ float selW[128];
    __shared__ int nsel;
    if (t == 0) nsel = 0;
    __syncthreads();
    const float inv = 1.0f / (1.0f + (float)NND * EPS_ATTN);
    if (t < nc) {
        float dv = dex[t];
        int idx = sidx[t];
        int rank = 0;
        for (int j = 0; j < nc; j++) {
            float dj = dex[j];
            if (dj > dv || (dj == dv && sidx[j] < idx)) rank++;
        }
        if (rank < kq) {
            int p = atomicAdd(&nsel, 1);
            if (p < 128) {
                selI[p] = idx;
                selW[p] = (expf(dv - M) / Z + EPS_ATTN) * inv;
            }
        }
    }
    __syncthreads();
    int nk = nsel < 128 ? nsel : 128;
    if (t < DD) {
        float acc = 0.0f;
        for (int sI = 0; sI < nk; sI++)
            acc = fmaf(selW[sI], g_qkv[(size_t)selI[sI] * 768 + 512 + t], acc);
        g_e2cat[row * 2 * DD + DD + t] = acc;
    }
}

// ----- node-side: softmax(dots2), screened exact top-k_e -> H, x_out ------
__global__ void __launch_bounds__(256) node_final(const float* __restrict__ x,
                                                  float* __restrict__ out,
                                                  const int* __restrict__ ke_ptr) {
    int row = blockIdx.x, t = threadIdx.x;
    const float* d2p = out + OFF_D2 + (size_t)row * NSS;
    __shared__ float d2s[512];
    float d0 = d2p[t], d1 = d2p[t + 256];
    d2s[t] = d0; d2s[t + 256] = d1;
    __shared__ float red[256];
    red[t] = fmaxf(d0, d1); __syncthreads();
    for (int s = 128; s > 0; s >>= 1) { if (t < s) red[t] = fmaxf(red[t], red[t + s]); __syncthreads(); }
    float M = red[0]; __syncthreads();
    float e0 = expf(d0 - M), e1 = expf(d1 - M);
    red[t] = e0 + e1; __syncthreads();
    for (int s = 128; s > 0; s >>= 1) { if (t < s) red[t] += red[t + s]; __syncthreads(); }
    float Z = red[0]; __syncthreads();

    const int SCREEN = 32;
    unsigned k0 = fkey(d0), k1 = fkey(d1);
    __shared__ unsigned h8[256];
    __shared__ unsigned sbb; __shared__ int srem;
    unsigned pref = 0, pmask = 0;
    int rem = SCREEN;
#pragma unroll
    for (int lvl = 0; lvl < 3; lvl++) {
        int sh = 24 - lvl * 8;
        h8[t] = 0;
        __syncthreads();
        if ((k0 & pmask) == pref) atomicAdd(&h8[(k0 >> sh) & 255], 1u);
        if ((k1 & pmask) == pref) atomicAdd(&h8[(k1 >> sh) & 255], 1u);
        __syncthreads();
        if (t == 0) {
            int cum = 0, b = 255;
            for (; b >= 0; b--) { cum += (int)h8[b]; if (cum >= rem) break; }
            if (b < 0) b = 0;
            sbb = (unsigned)b;
            srem = rem - (cum - (int)h8[b]);
        }
        __syncthreads();
        pref |= sbb << sh;
        pmask |= 255u << sh;
        rem = srem;
        __syncthreads();
    }

    __shared__ int cidx[64];
    __shared__ int ccnt;
    if (t == 0) ccnt = 0;
    __syncthreads();
    if (k0 >= pref) { int p = atomicAdd(&ccnt, 1); if (p < 64) cidx[p] = t; }
    if (k1 >= pref) { int p = atomicAdd(&ccnt, 1); if (p < 64) cidx[p] = t + 256; }
    __syncthreads();
    int nc = ccnt < 64 ? ccnt : 64;

    __shared__ float qs[256];
    qs[t] = g_qkv[(size_t)row * 768 + t];
    __syncthreads();
    __shared__ float dex[64];
    if (t < nc) {
        const float* k2p = g_k2 + (size_t)cidx[t] * DD;
        float acc = 0.0f;
#pragma unroll 8
        for (int k = 0; k < 256; k++) acc = fmaf(qs[k], k2p[k], acc);
        dex[t] = acc * 0.0625f;
    }
    __syncthreads();

    int ke = *ke_ptr;
    __shared__ int selList[16];
    __shared__ int nsel;
    if (t == 0) nsel = 0;
    __syncthreads();
    if (t < nc) {
        float dv = dex[t];
        int ci = cidx[t];
        int rank = 0;
        for (int j = 0; j < nc; j++) {
            float dj = dex[j];
            if (dj > dv || (dj == dv && cidx[j] < ci)) rank++;
        }
        if (rank < ke) {
            int p = atomicAdd(&nsel, 1);
            if (p < 16) selList[p] = ci;
        }
    }
    __syncthreads();
    int ns = nsel < 16 ? nsel : 16;

    __shared__ unsigned char flag[512];
    flag[t] = 0; flag[t + 256] = 0;
    __syncthreads();
    if (t < ns) flag[selList[t]] = 1;
    __syncthreads();

    float sv0 = e0 / Z, sv1 = e1 / Z;
    out[OFF_H + (size_t)row * NSS + t]       = flag[t]       ? sv0 : 0.0f;
    out[OFF_H + (size_t)row * NSS + t + 256] = flag[t + 256] ? sv1 : 0.0f;
    float acc = x[(size_t)row * DD + t];
    for (int sI = 0; sI < ns; sI++) {
        int col = selList[sI];
        float w = expf(d2s[col] - M) / Z;
        acc = fmaf(w, g_eout[col * DD + t], acc);
    }
    out[(size_t)row * DD + t] = acc;
}

// ------------------------- launch ----------------------------------------
extern "C" void kernel_launch(void* const* d_in, const int* in_sizes, int n_in,
                              void* d_out, int out_size) {
    const float* x    = (const float*)d_in[0];
    const float* noise= (const float*)d_in[1];
    const float* emu  = (const float*)d_in[2];
    const float* els  = (const float*)d_in[3];
    const float* lng  = (const float*)d_in[4];
    const float* lnb  = (const float*)d_in[5];
    const float* leg  = (const float*)d_in[6];
    const float* leb  = (const float*)d_in[7];
    const float* Wq = (const float*)d_in[8];  const float* bq = (const float*)d_in[9];
    const float* Wk = (const float*)d_in[10]; const float* bk = (const float*)d_in[11];
    const float* Wv = (const float*)d_in[12]; const float* bv = (const float*)d_in[13];
    const float* W1 = (const float*)d_in[14]; const float* b1 = (const float*)d_in[15];
    const float* W2 = (const float*)d_in[16]; const float* b2 = (const float*)d_in[17];
    const float* W  = (const float*)d_in[18]; const float* b  = (const float*)d_in[19];
    const int* knp  = (const int*)d_in[20];
    const int* kep  = (const int*)d_in[21];
    float* out = (float*)d_out;

    float *p_xin, *p_qkv, *p_dots, *p_qe, *p_k2, *p_eln, *p_e2, *p_h, *p_en, *p_wT, *p_bc, *p_eo;
    cudaGetSymbolAddress((void**)&p_xin, g_xin);
    cudaGetSymbolAddress((void**)&p_qkv, g_qkv);
    cudaGetSymbolAddress((void**)&p_dots, g_dots);
    cudaGetSymbolAddress((void**)&p_qe, g_qe);
    cudaGetSymbolAddress((void**)&p_k2, g_k2);
    cudaGetSymbolAddress((void**)&p_eln, g_eln);
    cudaGetSymbolAddress((void**)&p_e2, g_e2cat);
    cudaGetSymbolAddress((void**)&p_h, g_hmlp);
    cudaGetSymbolAddress((void**)&p_en, g_enew);
    cudaGetSymbolAddress((void**)&p_wT, g_wcatT);
    cudaGetSymbolAddress((void**)&p_bc, g_bcat);
    cudaGetSymbolAddress((void**)&p_eo, g_eout);

    __nv_bfloat16 *kkh, *kkl, *q2h, *q2l, *qeh, *qel, *k2h, *k2l;
    cudaGetSymbolAddress((void**)&kkh, g_kk_h); cudaGetSymbolAddress((void**)&kkl, g_kk_l);
    cudaGetSymbolAddress((void**)&q2h, g_q2_h); cudaGetSymbolAddress((void**)&q2l, g_q2_l);
    cudaGetSymbolAddress((void**)&qeh, g_qe_h); cudaGetSymbolAddress((void**)&qel, g_qe_l);
    cudaGetSymbolAddress((void**)&k2h, g_k2_h); cudaGetSymbolAddress((void**)&k2l, g_k2_l);

    const int TC_SMEM = 65536;   // 4 x 16KB swizzled tiles
    cudaFuncSetAttribute(tgemmL3, cudaFuncAttributeMaxDynamicSharedMemorySize, TC_SMEM);

    // 1) weight concat/transpose + biases
    prep_wcat<<<768, 256>>>(Wq, bq, Wk, bk, Wv, bv);
    // 2) node LN
    node_ln<<<NND, 256>>>(x, lng, lnb);
    // 3) edge sample + LN
    edge_prep<<<NSS, 256>>>(noise, emu, els, leg, leb);
    // 4) q_e = relu(e_ln @ Wq + bq)  [exact] + split
    rowgemm<<<NSS, 256>>>(p_eln, DD, DD, Wq, bq, p_qe, DD, 1);
    split_small<<<NSS, 256>>>(p_qe, qeh, qel);
    // 5) qkv exact scalar (kk/vv/q2 stay fp32-exact as the recompute anchor)
    {
        dim3 g(3 * DD / 128, NND / 128);
        sgemm_nt<<<g, 256>>>(p_xin, DD, p_wT, DD, p_qkv, 3 * DD, DD, p_bc, 1.0f, 256);
    }
    split_qkv<<<NND, 256>>>();
    // 6) dots = (q_e @ kk^T) * D^-0.5  [mma.sync+ldmatrix, 3-term]
    {
        dim3 g(NND / 128, NSS / 128);
        tgemmL3<<<g, 256, TC_SMEM>>>(qeh, qel, kkh, kkl, p_dots, NND, 0.0625f);
    }
    // 7) guarded edge selection + exact candidate recompute + gather
    edge_select<<<NSS, 1024>>>(knp);
    // 8) edge MLP + heads [exact] + k2 split
    rowgemm<<<NSS, 256>>>(p_e2, 2 * DD, 2 * DD, W1, b1, p_h, DD, 1);
    rowgemm<<<NSS, 256>>>(p_h, DD, DD, W2, b2, p_en, DD, 0);
    rowgemm<<<NSS, 256>>>(p_en, DD, DD, Wk, bk, p_k2, DD, 1);
    rowgemm<<<NSS, 256>>>(p_en, DD, DD, W, b, p_eo, DD, 0);
    split_small<<<NSS, 256>>>(p_k2, k2h, k2l);
    // 9) dots2 = (q2 @ k2^T) * D^-0.5 -> output slab  [mma.sync+ldmatrix, 3-term]
    {
        dim3 g(NSS / 128, NND / 128);
        tgemmL3<<<g, 256, TC_SMEM>>>(q2h, q2l, k2h, k2l, out + OFF_D2, NSS, 0.0625f);
    }
    // 10) screened exact top-k_e -> H + fused residual x_out
    node_final<<<NND, 256>>>(x, out, kep);
}

// round 17
// speedup vs baseline: 1.6078x; 1.6078x over previous
#include <cuda_runtime.h>
#include <math.h>
#include <stdint.h>

// Problem constants
#define NND   65536      // N nodes
#define DD    256        // feature dim
#define NSS   512        // edge slots
#define EPS_LN   1e-5f
#define EPS_ATTN 1e-8f

// Output layout: [x_out (N*D)] [H (N*NS)] [dots2 (N*NS)]
#define OFF_H   ((size_t)NND * DD)
#define OFF_D2  (OFF_H + (size_t)NND * NSS)

// ------------------------- device scratch (no allocations allowed) -------
__device__ float g_xin[(size_t)NND * DD];          // 64 MB  LN(x)
__device__ float g_qkv[(size_t)NND * 2 * DD];      // 128 MB [q2 | kk] row stride 512
__device__ float g_dots[(size_t)NSS * NND];        // 128 MB edge->node logits
__device__ float g_eln[NSS * DD];
__device__ float g_qe[NSS * DD];
__device__ float g_e2cat[NSS * 2 * DD];            // [e_ln | updates]
__device__ float g_hmlp[NSS * DD];
__device__ float g_enew[NSS * DD];
__device__ float g_k2[NSS * DD];
__device__ float g_eout[NSS * DD];
__device__ float g_wcatT[2 * DD * DD];             // [512][256]: row j = column j of (Wq|Wk)
__device__ float g_bcat[2 * DD];

// ------------------------- small helpers ---------------------------------
__device__ __forceinline__ unsigned fkey(float f) {
    unsigned u = __float_as_uint(f);
    return (u & 0x80000000u) ? ~u : (u | 0x80000000u); // order-preserving map
}

// ------------------------- weight prep -----------------------------------
__global__ void prep_wcat(const float* __restrict__ Wq, const float* __restrict__ bq,
                          const float* __restrict__ Wk, const float* __restrict__ bk) {
    int idx = blockIdx.x * 256 + threadIdx.x;     // 512*256 total
    int j = idx >> 8, k = idx & 255;
    const float* W = (j < 256) ? Wq : Wk;
    int jj = j & 255;
    g_wcatT[idx] = W[k * 256 + jj];
    if (k == 0) g_bcat[j] = (j < 256) ? bq[jj] : bk[jj];
}

// ------------------------- row LayerNorm (nodes) --------------------------
__global__ void node_ln(const float* __restrict__ x, const float* __restrict__ g,
                        const float* __restrict__ b) {
    int row = blockIdx.x, t = threadIdx.x;   // 256 threads
    __shared__ float red[256];
    float v = x[(size_t)row * DD + t];
    red[t] = v; __syncthreads();
    for (int s = 128; s > 0; s >>= 1) { if (t < s) red[t] += red[t + s]; __syncthreads(); }
    float mean = red[0] * (1.0f / DD);
    __syncthreads();
    float d = v - mean;
    red[t] = d * d; __syncthreads();
    for (int s = 128; s > 0; s >>= 1) { if (t < s) red[t] += red[t + s]; __syncthreads(); }
    float var = red[0] * (1.0f / DD);
    g_xin[(size_t)row * DD + t] = d * rsqrtf(var + EPS_LN) * g[t] + b[t];
}

// ------------------------- edge prep: sample + LN -------------------------
__global__ void edge_prep(const float* __restrict__ noise, const float* __restrict__ mu,
                          const float* __restrict__ ls, const float* __restrict__ g,
                          const float* __restrict__ b) {
    int row = blockIdx.x, t = threadIdx.x;   // 512 blocks x 256 threads
    __shared__ float red[256];
    float v = mu[t] + expf(ls[t]) * noise[row * DD + t];
    red[t] = v; __syncthreads();
    for (int s = 128; s > 0; s >>= 1) { if (t < s) red[t] += red[t + s]; __syncthreads(); }
    float mean = red[0] * (1.0f / DD);
    __syncthreads();
    float d = v - mean;
    red[t] = d * d; __syncthreads();
    for (int s = 128; s > 0; s >>= 1) { if (t < s) red[t] += red[t + s]; __syncthreads(); }
    float var = red[0] * (1.0f / DD);
    float o = d * rsqrtf(var + EPS_LN) * g[t] + b[t];
    g_eln[row * DD + t] = o;
    g_e2cat[row * 2 * DD + t] = o;
}

// ------------- small dense: one row per block, 256 output cols ------------
__global__ void rowgemm(const float* __restrict__ X, int ldx, int K,
                        const float* __restrict__ Wm, const float* __restrict__ bias,
                        float* __restrict__ Y, int ldy, int relu) {
    __shared__ float xr[512];
    int row = blockIdx.x, t = threadIdx.x;
    for (int i = t; i < K; i += 256) xr[i] = X[(size_t)row * ldx + i];
    __syncthreads();
    float acc = bias[t];
    for (int k = 0; k < K; k++) acc = fmaf(xr[k], Wm[k * 256 + t], acc);
    if (relu) acc = fmaxf(acc, 0.0f);
    Y[(size_t)row * ldy + t] = acc;
}

// ------------------------- big SGEMM: C = scale*A*B^T (+bias, relu) -------
// A[M,K] lda, B[N,K] ldb (K-contiguous), C[M,N] ldc. K % 16 == 0,
// M,N % 128 == 0. 128x128x16 tile, double-buffered, 256 threads, 8x8 micro.
// fp32 FFMA, sequential k-order accumulation (bitwise-stable numerics).
__global__ void __launch_bounds__(256, 2) sgemm_nt(
        const float* __restrict__ A, int lda,
        const float* __restrict__ B, int ldb,
        float* __restrict__ C, int ldc, int K,
        const float* __restrict__ bias, float scale, int relu_from) {
    __shared__ float As[2][16][132];
    __shared__ float Bs[2][16][132];
    const int tid = threadIdx.x;
    const int bm = blockIdx.y * 128, bn = blockIdx.x * 128;
    const int tx = tid & 15, ty = tid >> 4;
    const int lr = tid & 127;
    const int lk = (tid >> 7) * 8;
    const float* Ag = A + (size_t)(bm + lr) * lda + lk;
    const float* Bg = B + (size_t)(bn + lr) * ldb + lk;

    float acc[8][8] = {};
    float4 a0 = *(const float4*)(Ag);
    float4 a1 = *(const float4*)(Ag + 4);
    float4 b0 = *(const float4*)(Bg);
    float4 b1 = *(const float4*)(Bg + 4);
    As[0][lk + 0][lr] = a0.x; As[0][lk + 1][lr] = a0.y;
    As[0][lk + 2][lr] = a0.z; As[0][lk + 3][lr] = a0.w;
    As[0][lk + 4][lr] = a1.x; As[0][lk + 5][lr] = a1.y;
    As[0][lk + 6][lr] = a1.z; As[0][lk + 7][lr] = a1.w;
    Bs[0][lk + 0][lr] = b0.x; Bs[0][lk + 1][lr] = b0.y;
    Bs[0][lk + 2][lr] = b0.z; Bs[0][lk + 3][lr] = b0.w;
    Bs[0][lk + 4][lr] = b1.x; Bs[0][lk + 5][lr] = b1.y;
    Bs[0][lk + 6][lr] = b1.z; Bs[0][lk + 7][lr] = b1.w;
    __syncthreads();

    const int nIter = K >> 4;
    for (int it = 0; it < nIter; it++) {
        const int cur = it & 1;
        if (it + 1 < nIter) {
            int k0 = (it + 1) << 4;
            a0 = *(const float4*)(Ag + k0);
            a1 = *(const float4*)(Ag + k0 + 4);
            b0 = *(const float4*)(Bg + k0);
            b1 = *(const float4*)(Bg + k0 + 4);
        }
#pragma unroll
        for (int kk = 0; kk < 16; kk++) {
            float a[8], b[8];
            *(float4*)(a)     = *(const float4*)&As[cur][kk][ty * 4];
            *(float4*)(a + 4) = *(const float4*)&As[cur][kk][64 + ty * 4];
            *(float4*)(b)     = *(const float4*)&Bs[cur][kk][tx * 4];
            *(float4*)(b + 4) = *(const float4*)&Bs[cur][kk][64 + tx * 4];
#pragma unroll
            for (int i = 0; i < 8; i++)
#pragma unroll
                for (int j = 0; j < 8; j++)
                    acc[i][j] = fmaf(a[i], b[j], acc[i][j]);
        }
        if (it + 1 < nIter) {
            const int nxt = cur ^ 1;
            As[nxt][lk + 0][lr] = a0.x; As[nxt][lk + 1][lr] = a0.y;
            As[nxt][lk + 2][lr] = a0.z; As[nxt][lk + 3][lr] = a0.w;
            As[nxt][lk + 4][lr] = a1.x; As[nxt][lk + 5][lr] = a1.y;
            As[nxt][lk + 6][lr] = a1.z; As[nxt][lk + 7][lr] = a1.w;
            Bs[nxt][lk + 0][lr] = b0.x; Bs[nxt][lk + 1][lr] = b0.y;
            Bs[nxt][lk + 2][lr] = b0.z; Bs[nxt][lk + 3][lr] = b0.w;
            Bs[nxt][lk + 4][lr] = b1.x; Bs[nxt][lk + 5][lr] = b1.y;
            Bs[nxt][lk + 6][lr] = b1.z; Bs[nxt][lk + 7][lr] = b1.w;
            __syncthreads();
        }
    }
#pragma unroll
    for (int ih = 0; ih < 2; ih++) {
#pragma unroll
        for (int i = 0; i < 4; i++) {
            int row = bm + ih * 64 + ty * 4 + i;
#pragma unroll
            for (int jh = 0; jh < 2; jh++) {
                int col = bn + jh * 64 + tx * 4;
                float4 v;
                float* vp = (float*)&v;
#pragma unroll
                for (int j = 0; j < 4; j++) {
                    float t = acc[ih * 4 + i][jh * 4 + j] * scale;
                    if (bias) t += bias[col + j];
                    if (col + j >= relu_from) t = fmaxf(t, 0.0f);
                    vp[j] = t;
                }
                *(float4*)&C[(size_t)row * ldc + col] = v;
            }
        }
    }
}

// ----- edge-side: softmax stats + exact top-k_n + ON-DEMAND vv update -----
// 4 sweeps of the dots row: fused(max/sum + hist0), hist1, hist2, select.
// Then vv for the <=128 selected rows is computed on the fly:
//   updates[t] = sum_s w_s * relu(xin[s,:] . Wv[:,t] + bv[t])
// Phase-A smem (radix: red 4KB + hist 8KB) is union'd with
// phase-B smem (xs 33KB + updp 4KB) to stay under the 48KB static limit.
__global__ void __launch_bounds__(1024) edge_select(const int* __restrict__ kn_ptr,
                                                    const float* __restrict__ Wv,
                                                    const float* __restrict__ bv) {
    const int row = blockIdx.x;
    const int t = threadIdx.x;                    // 1024 threads
    const float* dr = g_dots + (size_t)row * NND;
    __shared__ char uni[37120];                   // phase A: red|hist, phase B: xs|updp
    float* red = (float*)uni;                     // [1024]
    unsigned* hist = (unsigned*)(uni + 4096);     // [2048]
    __shared__ unsigned sb_bin;
    __shared__ int sb_rem;
    __shared__ int cnt, cnteq;
    __shared__ int   sidx[128];
    __shared__ float sw[128];

    // pass 0 (fused): online max / sum-exp  +  histogram of bits [31:21)
    for (int i = t; i < 2048; i += 1024) hist[i] = 0;
    __syncthreads();
    float m = -3.0e38f, s = 0.0f;
    for (int i = t; i < NND; i += 1024) {
        float dv = dr[i];
        if (dv > m) { s = s * expf(m - dv) + 1.0f; m = dv; }
        else        { s += expf(dv - m); }
        atomicAdd(&hist[fkey(dv) >> 21], 1u);
    }
    red[t] = m; __syncthreads();
    for (int st = 512; st > 0; st >>= 1) { if (t < st) red[t] = fmaxf(red[t], red[t + st]); __syncthreads(); }
    float M = red[0]; __syncthreads();
    red[t] = s * expf(m - M); __syncthreads();
    for (int st = 512; st > 0; st >>= 1) { if (t < st) red[t] += red[t + st]; __syncthreads(); }
    float Z = red[0]; __syncthreads();

    int kq = *kn_ptr;
    unsigned pref = 0, pmask = 0;
    int rem = kq;
    if (t == 0) {
        int cum = 0, b = 2047;
        for (; b >= 0; b--) { cum += (int)hist[b]; if (cum >= rem) break; }
        if (b < 0) b = 0;
        sb_bin = (unsigned)b;
        sb_rem = rem - (cum - (int)hist[b]);
    }
    __syncthreads();
    pref = sb_bin << 21;
    pmask = 2047u << 21;
    rem = sb_rem;
    __syncthreads();

    // refinement passes: bits [21:10) then [10:0)
    const int shifts[2] = {10, 0};
    const int bcnts[2]  = {2048, 1024};
    for (int p = 0; p < 2; p++) {
        int bc = bcnts[p], sh = shifts[p];
        for (int i = t; i < bc; i += 1024) hist[i] = 0;
        __syncthreads();
        for (int i = t; i < NND; i += 1024) {
            unsigned key = fkey(dr[i]);
            if ((key & pmask) == pref) atomicAdd(&hist[(key >> sh) & (bc - 1)], 1u);
        }
        __syncthreads();
        if (t == 0) {
            int cum = 0, b = bc - 1;
            for (; b >= 0; b--) { cum += (int)hist[b]; if (cum >= rem) break; }
            if (b < 0) b = 0;
            sb_bin = (unsigned)b;
            sb_rem = rem - (cum - (int)hist[b]);
        }
        __syncthreads();
        pref |= sb_bin << sh;
        pmask |= (unsigned)(bc - 1) << sh;
        rem = sb_rem;
        __syncthreads();
    }

    // select: all keys > pref, plus `rem` keys == pref
    if (t == 0) { cnt = 0; cnteq = 0; }
    __syncthreads();
    const float inv = 1.0f / (1.0f + (float)NND * EPS_ATTN);
    for (int i = t; i < NND; i += 1024) {
        float dv = dr[i];
        unsigned key = fkey(dv);
        bool take = false;
        if (key > pref) take = true;
        else if (key == pref) { int e = atomicAdd(&cnteq, 1); if (e < rem) take = true; }
        if (take) {
            int p = atomicAdd(&cnt, 1);
            if (p < 128) {
                sidx[p] = i;
                sw[p] = (expf(dv - M) / Z + EPS_ATTN) * inv;
            }
        }
    }
    __syncthreads();
    int nk = cnt < 128 ? cnt : 128;

    // phase B: on-demand vv + weighted accumulate (reuses uni[] space)
    float (*xs)[258] = (float(*)[258])uni;             // [32][258] = 33024 B
    float (*updp)[256] = (float(*)[256])(uni + 33024); // [4][256] = 4096 B
    const int grp = t >> 8, col = t & 255;
    float upd = 0.0f;
    for (int c0 = 0; c0 < nk; c0 += 32) {
        int nr = nk - c0; if (nr > 32) nr = 32;
        for (int i = t; i < nr * 256; i += 1024) {
            int sl = i >> 8, k = i & 255;
            xs[sl][k] = g_xin[(size_t)sidx[c0 + sl] * DD + k];
        }
        __syncthreads();
        float accs[8];
#pragma unroll
        for (int i = 0; i < 8; i++) accs[i] = bv[col];
        for (int k = 0; k < 256; k += 2) {
            float w0 = Wv[k * 256 + col];
            float w1 = Wv[(k + 1) * 256 + col];
#pragma unroll
            for (int i = 0; i < 8; i++) {
                float2 xv = *(float2*)&xs[grp + i * 4][k];
                accs[i] = fmaf(xv.x, w0, accs[i]);
                accs[i] = fmaf(xv.y, w1, accs[i]);
            }
        }
#pragma unroll
        for (int i = 0; i < 8; i++) {
            int sl = grp + i * 4;
            if (sl < nr) upd = fmaf(sw[c0 + sl], fmaxf(accs[i], 0.0f), upd);
        }
        __syncthreads();
    }
    updp[grp][col] = upd;
    __syncthreads();
    if (t < 256)
        g_e2cat[row * 2 * DD + DD + t] =
            updp[0][t] + updp[1][t] + updp[2][t] + updp[3][t];
}

// ----- node-side: softmax(dots2), top-k_e -> H, fused residual x_out -------
__global__ void __launch_bounds__(256) node_final(const float* __restrict__ x,
                                                  float* __restrict__ out,
                                                  const int* __restrict__ ke_ptr) {
    int row = blockIdx.x, t = threadIdx.x;  // 256 threads
    const float* d2 = out + OFF_D2 + (size_t)row * NSS;
    float d0 = d2[t], d1 = d2[t + 256];
    __shared__ float red[256];
    red[t] = fmaxf(d0, d1); __syncthreads();
    for (int s = 128; s > 0; s >>= 1) { if (t < s) red[t] = fmaxf(red[t], red[t + s]); __syncthreads(); }
    float M = red[0]; __syncthreads();
    float e0 = expf(d0 - M), e1 = expf(d1 - M);
    red[t] = e0 + e1; __syncthreads();
    for (int s = 128; s > 0; s >>= 1) { if (t < s) red[t] += red[t + s]; __syncthreads(); }
    float Z = red[0]; __syncthreads();

    __shared__ float sv[512];
    __shared__ int fl[512];
    sv[t] = e0 / Z; sv[t + 256] = e1 / Z;
    fl[t] = 0; fl[t + 256] = 0;
    __syncthreads();

    int ke = *ke_ptr;
    __shared__ float rv[256]; __shared__ int ri[256];
    __shared__ int   selI[16]; __shared__ float selW[16];
    for (int it = 0; it < ke && it < 16; it++) {
        float bv = -1.0f; int bi = -1;
        if (!fl[t] && sv[t] > bv) { bv = sv[t]; bi = t; }
        if (!fl[t + 256] && sv[t + 256] > bv) { bv = sv[t + 256]; bi = t + 256; }
        rv[t] = bv; ri[t] = bi; __syncthreads();
        for (int st = 128; st > 0; st >>= 1) {
            if (t < st && rv[t + st] > rv[t]) { rv[t] = rv[t + st]; ri[t] = ri[t + st]; }
            __syncthreads();
        }
        if (t == 0) { selI[it] = ri[0]; selW[it] = rv[0]; fl[ri[0]] = 1; }
        __syncthreads();
    }
    out[OFF_H + (size_t)row * NSS + t]       = fl[t]       ? sv[t]       : 0.0f;
    out[OFF_H + (size_t)row * NSS + t + 256] = fl[t + 256] ? sv[t + 256] : 0.0f;
    float acc = x[(size_t)row * DD + t];
    for (int it = 0; it < ke && it < 16; it++)
        acc = fmaf(selW[it], g_eout[selI[it] * DD + t], acc);
    out[(size_t)row * DD + t] = acc;
}

// ------------------------- launch ----------------------------------------
extern "C" void kernel_launch(void* const* d_in, const int* in_sizes, int n_in,
                              void* d_out, int out_size) {
    const float* x    = (const float*)d_in[0];
    const float* noise= (const float*)d_in[1];
    const float* emu  = (const float*)d_in[2];
    const float* els  = (const float*)d_in[3];
    const float* lng  = (const float*)d_in[4];
    const float* lnb  = (const float*)d_in[5];
    const float* leg  = (const float*)d_in[6];
    const float* leb  = (const float*)d_in[7];
    const float* Wq = (const float*)d_in[8];  const float* bq = (const float*)d_in[9];
    const float* Wk = (const float*)d_in[10]; const float* bk = (const float*)d_in[11];
    const float* Wv = (const float*)d_in[12]; const float* bv = (const float*)d_in[13];
    const float* W1 = (const float*)d_in[14]; const float* b1 = (const float*)d_in[15];
    const float* W2 = (const float*)d_in[16]; const float* b2 = (const float*)d_in[17];
    const float* W  = (const float*)d_in[18]; const float* b  = (const float*)d_in[19];
    const int* knp  = (const int*)d_in[20];
    const int* kep  = (const int*)d_in[21];
    float* out = (float*)d_out;

    // scratch pointers (symbol lookups; no stream work, capture-safe)
    float *p_xin, *p_qkv, *p_dots, *p_qe, *p_k2, *p_eln, *p_e2, *p_h, *p_en, *p_wT, *p_bc, *p_eo;
    cudaGetSymbolAddress((void**)&p_xin, g_xin);
    cudaGetSymbolAddress((void**)&p_qkv, g_qkv);
    cudaGetSymbolAddress((void**)&p_dots, g_dots);
    cudaGetSymbolAddress((void**)&p_qe, g_qe);
    cudaGetSymbolAddress((void**)&p_k2, g_k2);
    cudaGetSymbolAddress((void**)&p_eln, g_eln);
    cudaGetSymbolAddress((void**)&p_e2, g_e2cat);
    cudaGetSymbolAddress((void**)&p_h, g_hmlp);
    cudaGetSymbolAddress((void**)&p_en, g_enew);
    cudaGetSymbolAddress((void**)&p_wT, g_wcatT);
    cudaGetSymbolAddress((void**)&p_bc, g_bcat);
    cudaGetSymbolAddress((void**)&p_eo, g_eout);

    // 1) weight concat/transpose (Wq|Wk only) + biases
    prep_wcat<<<512, 256>>>(Wq, bq, Wk, bk);
    // 2) node LN
    node_ln<<<NND, 256>>>(x, lng, lnb);
    // 3) edge sample + LN (also fills e2cat[:, :256])
    edge_prep<<<NSS, 256>>>(noise, emu, els, leg, leb);
    // 4) q_e = relu(e_ln @ Wq + bq)
    rowgemm<<<NSS, 256>>>(p_eln, DD, DD, Wq, bq, p_qe, DD, 1);
    // 5) [q2|kk] = xin @ WcatT^T + bcat, relu on cols >= 256 (kk only)
    {
        dim3 g(2 * DD / 128, NND / 128);
        sgemm_nt<<<g, 256>>>(p_xin, DD, p_wT, DD, p_qkv, 2 * DD, DD, p_bc, 1.0f, 256);
    }
    // 6) dots = (q_e @ kk^T) * D^-0.5
    {
        dim3 g(NND / 128, NSS / 128);
        sgemm_nt<<<g, 256>>>(p_qe, DD, p_qkv + 256, 2 * DD, p_dots, NND, DD,
                             nullptr, 0.0625f, 1 << 30);
    }
    // 7) per-edge softmax + exact top-k_n + on-demand vv weighted gather
    edge_select<<<NSS, 1024>>>(knp, Wv, bv);
    // 8) edge MLP + heads
    rowgemm<<<NSS, 256>>>(p_e2, 2 * DD, 2 * DD, W1, b1, p_h, DD, 1);   // hidden
    rowgemm<<<NSS, 256>>>(p_h, DD, DD, W2, b2, p_en, DD, 0);           // e_new
    rowgemm<<<NSS, 256>>>(p_en, DD, DD, Wk, bk, p_k2, DD, 1);          // k2
    rowgemm<<<NSS, 256>>>(p_en, DD, DD, W, b, p_eo, DD, 0);            // e_out
    // 9) dots2 = (q2 @ k2^T) * D^-0.5 -> straight into output slab
    {
        dim3 g(NSS / 128, NND / 128);
        sgemm_nt<<<g, 256>>>(p_qkv, 2 * DD, p_k2, DD, out + OFF_D2, NSS, DD,
                             nullptr, 0.0625f, 1 << 30);
    }
    // 10) per-node softmax + top-k_e -> H, fused residual x_out
    node_final<<<NND, 256>>>(x, out, kep);
}